// round 13
// baseline (speedup 1.0000x reference)
#include <cuda_runtime.h>
#include <cuda_fp16.h>
#include <cstdint>

// ============================================================================
// ConvolutionFromEdgeSetUpdate:
//   messages = relu([node[src] | node[tgt] | edge] @ W + b)   (E x 64)
//   out      = segment_sum(messages, tgt, 50000)
// E=800000, D=64, U=64, K=192.
//
// R13 = R11 (single fp16 product, 2-stage pipeline, 1 barrier/tile) with
// UNPADDED 384B rows + per-row XOR swizzle of 16B chunks (chunk ^ (row&7)).
// SMEM 77.8 -> 73.0 KB/CTA => 3 CTAs/SM (24 warps, +50% latency coverage).
// ldsm/STS bank behavior identical to the padded layout.
// ============================================================================

#define NN_NODES 50000
#define NN_EDGES 800000
#define D_FEAT   64
#define UNITS    64
#define KDIM     192
#define TILE_M   64
#define N_TILES  (NN_EDGES / TILE_M)   // 12500
#define THREADS  256                   // 8 warps: 4 mg x 2 ng
#define GRID_X   444                   // 3 CTAs per SM

#define ROWB     384                   // exact row bytes (192 fp16), no pad
#define SM_A0    0
#define SM_A1    (SM_A0 + TILE_M * ROWB)     // 24576
#define SM_B     (SM_A1 + TILE_M * ROWB)     // 49152
#define SM_IDX   (SM_B + UNITS * ROWB)       // 73728: 2 bufs x 128 int
#define SM_TOTAL (SM_IDX + 2 * 128 * 4)      // 74752 -> 3 CTAs/SM

// ---------------- helpers ----------------

__device__ __forceinline__ uint32_t smem_to_u32(const void* smem_ptr) {
    uint32_t addr;
    asm("{ .reg .u64 tmp; cvta.to.shared.u64 tmp, %1; cvt.u32.u64 %0, tmp; }"
        : "=r"(addr) : "l"(smem_ptr));
    return addr;
}

__device__ __forceinline__ void ldsm_x4(uint32_t* r, uint32_t addr) {
    asm volatile("ldmatrix.sync.aligned.m8n8.x4.shared.b16 {%0,%1,%2,%3}, [%4];"
        : "=r"(r[0]), "=r"(r[1]), "=r"(r[2]), "=r"(r[3]) : "r"(addr));
}

__device__ __forceinline__ void ldsm_x2(uint32_t* r, uint32_t addr) {
    asm volatile("ldmatrix.sync.aligned.m8n8.x2.shared.b16 {%0,%1}, [%2];"
        : "=r"(r[0]), "=r"(r[1]) : "r"(addr));
}

__device__ __forceinline__ void mma_f16(float* c, const uint32_t* a, const uint32_t* b) {
    asm volatile(
        "mma.sync.aligned.m16n8k16.row.col.f32.f16.f16.f32 "
        "{%0,%1,%2,%3}, {%4,%5,%6,%7}, {%8,%9}, {%0,%1,%2,%3};"
        : "+f"(c[0]), "+f"(c[1]), "+f"(c[2]), "+f"(c[3])
        : "r"(a[0]), "r"(a[1]), "r"(a[2]), "r"(a[3]), "r"(b[0]), "r"(b[1]));
}

__device__ __forceinline__ uint32_t pack_h2(float a, float b) {
    __half2 t = __halves2half2(__float2half_rn(a), __float2half_rn(b));
    return *reinterpret_cast<uint32_t*>(&t);
}

// ---------------- zero output (d_out is poisoned 0xAA) ----------------

__global__ void zero_out_kernel(float4* out) {
    int i = blockIdx.x * blockDim.x + threadIdx.x;
    if (i < NN_NODES * UNITS / 4) out[i] = make_float4(0.f, 0.f, 0.f, 0.f);
}

// ---------------- main fused kernel ----------------

__global__ __launch_bounds__(THREADS, 3)
void edgeconv_kernel(const float* __restrict__ node_feat,
                     const float* __restrict__ edge_feat,
                     const int*   __restrict__ src_idx,
                     const int*   __restrict__ tgt_idx,
                     const float* __restrict__ W,
                     const float* __restrict__ bias,
                     float*       __restrict__ out)
{
    extern __shared__ char smem[];
    const uint32_t smem_base = smem_to_u32(smem);
    const int tid  = threadIdx.x;
    const int wid  = tid >> 5;
    const int lane = tid & 31;

    int* const idx_sm = reinterpret_cast<int*>(smem + SM_IDX);

    // ---- build B = W^T (fp16) in SMEM, swizzled rows ----
    // Bsm row n, element k at: n*ROWB + ((k>>3) ^ (n&7))*16 + (k&7)*2
    for (int task = tid; task < 192; task += THREADS) {
        const int n = task & 63, bseg = task >> 6;
        char* rowp = smem + SM_B + n * ROWB;
        const int n7 = n & 7;
        #pragma unroll 8
        for (int j = 0; j < 64; ++j) {
            const int k = bseg * 64 + j;
            const uint32_t off = (uint32_t)((((k >> 3) ^ n7) << 4) + (k & 7) * 2);
            *reinterpret_cast<__half*>(rowp + off) = __float2half_rn(W[k * UNITS + n]);
        }
    }

    // warp tile: mg in {0..3} picks 16 rows, ng in {0,1} picks 32 cols
    const int mg = wid >> 1;
    const int ng = wid & 1;
    const int t4 = lane & 3;
    const int g  = lane >> 2;
    const int r0 = mg * 16 + g;           // epilogue row within tile (0..63)

    // per-thread bias: cols ng*32 + j*8 + 2*t4 + {0,1}
    float bj0[4], bj1[4];
    #pragma unroll
    for (int j = 0; j < 4; ++j) {
        bj0[j] = bias[ng * 32 + j * 8 + 2 * t4];
        bj1[j] = bias[ng * 32 + j * 8 + 2 * t4 + 1];
    }

    // ldmatrix lane components (swizzled addressing computed per k-step)
    const int l7 = lane & 7;
    const int ha = lane >> 4;             // A: 16B half select
    const int hb = (lane >> 3) & 1;       // B: 16B half select
    const uint32_t aRowTerm = (uint32_t)((mg * 16 + (lane & 15)) * ROWB);
    uint32_t bRow[4];
    #pragma unroll
    for (int nb = 0; nb < 4; ++nb)
        bRow[nb] = smem_base + SM_B
                 + (uint32_t)((ng * 32 + nb * 8 + l7) * ROWB);

    // coalesced gather mapping: 16 threads per (row,seg), one float4 each
    const int g_chunk = tid & 15;          // float4 index within 64-float row
    const int g_rs0   = tid >> 4;          // first rowseg (0..15), step 16

    // ======== prologue: idx(t0) -> buf0 ========
    const int tile0 = blockIdx.x;
    if (tid < 128) {
        const int e = tile0 * TILE_M + (tid & 63);
        idx_sm[tid] = (tid < 64) ? __ldg(src_idx + e) : __ldg(tgt_idx + e);
    }
    __syncthreads();   // B + idx(t0) ready

    // gather(t0) -> A buf0
    {
        const int* idxp = idx_sm;          // buf 0
        #pragma unroll
        for (int half = 0; half < 2; ++half) {
            const float* p[6]; int rowv[6], segv[6];
            #pragma unroll
            for (int i = 0; i < 6; ++i) {
                const int rs  = g_rs0 + (half * 6 + i) * 16;
                const int row = rs & (TILE_M - 1);
                const int seg = rs >> 6;
                rowv[i] = row; segv[i] = seg;
                p[i] = (seg == 2)
                     ? edge_feat + (size_t)(tile0 * TILE_M + row) * D_FEAT
                     : node_feat + (size_t)idxp[rs] * D_FEAT;
            }
            float4 v[6];
            #pragma unroll
            for (int i = 0; i < 6; ++i)
                v[i] = __ldg(reinterpret_cast<const float4*>(p[i]) + g_chunk);
            #pragma unroll
            for (int i = 0; i < 6; ++i) {
                uint2 hh;
                hh.x = pack_h2(v[i].x, v[i].y);
                hh.y = pack_h2(v[i].z, v[i].w);
                const int c16 = segv[i] * 8 + (g_chunk >> 1);
                const uint32_t off = (uint32_t)(rowv[i] * ROWB
                    + ((c16 ^ (rowv[i] & 7)) << 4) + (g_chunk & 1) * 8);
                *reinterpret_cast<uint2*>(smem + SM_A0 + off) = hh;
            }
        }
    }
    int tgtr0 = idx_sm[64 + r0];
    int tgtr1 = idx_sm[64 + r0 + 8];
    if (tid < 128 && tile0 + GRID_X < N_TILES) {
        const int e = (tile0 + GRID_X) * TILE_M + (tid & 63);
        idx_sm[128 + tid] = (tid < 64) ? __ldg(src_idx + e) : __ldg(tgt_idx + e);
    }
    __syncthreads();   // A buf0 + idx(t0+G) ready

    // ======== pipelined main loop: one barrier per tile ========
    int p = 0, q = 0;
    for (int tile = tile0; tile < N_TILES; tile += GRID_X) {
        const int nxt = tile + GRID_X;
        int ntgt0 = 0, ntgt1 = 0;

        // ---- stage 1: gather(nxt) into A buf p^1 (LDGs overlap MMA below) --
        if (nxt < N_TILES) {
            const int* idxp = idx_sm + (q ^ 1) * 128;
            const uint32_t abase = (p ^ 1) ? SM_A1 : SM_A0;
            #pragma unroll
            for (int half = 0; half < 2; ++half) {
                const float* pp[6]; int rowv[6], segv[6];
                #pragma unroll
                for (int i = 0; i < 6; ++i) {
                    const int rs  = g_rs0 + (half * 6 + i) * 16;
                    const int row = rs & (TILE_M - 1);
                    const int seg = rs >> 6;
                    rowv[i] = row; segv[i] = seg;
                    pp[i] = (seg == 2)
                         ? edge_feat + (size_t)(nxt * TILE_M + row) * D_FEAT
                         : node_feat + (size_t)idxp[rs] * D_FEAT;
                }
                float4 v[6];
                #pragma unroll
                for (int i = 0; i < 6; ++i)
                    v[i] = __ldg(reinterpret_cast<const float4*>(pp[i]) + g_chunk);
                #pragma unroll
                for (int i = 0; i < 6; ++i) {
                    uint2 hh;
                    hh.x = pack_h2(v[i].x, v[i].y);
                    hh.y = pack_h2(v[i].z, v[i].w);
                    const int c16 = segv[i] * 8 + (g_chunk >> 1);
                    const uint32_t off = (uint32_t)(rowv[i] * ROWB
                        + ((c16 ^ (rowv[i] & 7)) << 4) + (g_chunk & 1) * 8);
                    *reinterpret_cast<uint2*>(smem + abase + off) = hh;
                }
            }
            ntgt0 = idxp[64 + r0];
            ntgt1 = idxp[64 + r0 + 8];
            if (tid < 128 && nxt + GRID_X < N_TILES) {
                const int e = (nxt + GRID_X) * TILE_M + (tid & 63);
                idx_sm[q * 128 + tid] =
                    (tid < 64) ? __ldg(src_idx + e) : __ldg(tgt_idx + e);
            }
        }

        // ---- stage 2: MMA(tile) from A buf p ----
        const uint32_t aRow = smem_base + (p ? SM_A1 : SM_A0) + aRowTerm;
        float acc[4][4];
        #pragma unroll
        for (int j = 0; j < 4; ++j) {
            acc[j][0] = 0.f; acc[j][1] = 0.f; acc[j][2] = 0.f; acc[j][3] = 0.f;
        }
        #pragma unroll
        for (int ks = 0; ks < KDIM / 16; ++ks) {   // 12 k-steps
            const uint32_t swA = (uint32_t)((((ks << 1) + ha) ^ l7) << 4);
            const uint32_t swB = (uint32_t)((((ks << 1) + hb) ^ l7) << 4);
            uint32_t aa[4];
            ldsm_x4(aa, aRow + swA);
            #pragma unroll
            for (int j = 0; j < 4; ++j) {
                uint32_t bb[2];
                ldsm_x2(bb, bRow[j] + swB);
                mma_f16(acc[j], aa, bb);
            }
        }

        // ---- epilogue(tile): bias + relu + red.v2 scatter ----
        {
            float* o0 = out + (size_t)tgtr0 * UNITS + ng * 32 + 2 * t4;
            float* o1 = out + (size_t)tgtr1 * UNITS + ng * 32 + 2 * t4;
            #pragma unroll
            for (int j = 0; j < 4; ++j) {
                float v0 = fmaxf(acc[j][0] + bj0[j], 0.f);
                float v1 = fmaxf(acc[j][1] + bj1[j], 0.f);
                float v2 = fmaxf(acc[j][2] + bj0[j], 0.f);
                float v3 = fmaxf(acc[j][3] + bj1[j], 0.f);
                asm volatile("red.global.add.v2.f32 [%0], {%1, %2};"
                             :: "l"(o0 + j * 8), "f"(v0), "f"(v1) : "memory");
                asm volatile("red.global.add.v2.f32 [%0], {%1, %2};"
                             :: "l"(o1 + j * 8), "f"(v2), "f"(v3) : "memory");
            }
        }

        __syncthreads();   // A buf p^1 written, idx buf q staged, buf p free
        tgtr0 = ntgt0; tgtr1 = ntgt1;
        p ^= 1; q ^= 1;
    }
}

// ---------------- launch ----------------

extern "C" void kernel_launch(void* const* d_in, const int* in_sizes, int n_in,
                              void* d_out, int out_size) {
    const float* node_feat = (const float*)d_in[0];
    const float* edge_feat = (const float*)d_in[1];
    const int*   src_idx   = (const int*)d_in[2];
    const int*   tgt_idx   = (const int*)d_in[3];
    const float* W         = (const float*)d_in[4];
    const float* b         = (const float*)d_in[5];
    float* out = (float*)d_out;

    int n4 = NN_NODES * UNITS / 4;
    zero_out_kernel<<<(n4 + 255) / 256, 256>>>((float4*)out);

    static int configured = 0;
    if (!configured) {
        cudaFuncSetAttribute(edgeconv_kernel,
                             cudaFuncAttributeMaxDynamicSharedMemorySize, SM_TOTAL);
        configured = 1;
    }
    edgeconv_kernel<<<GRID_X, THREADS, SM_TOTAL>>>(
        node_feat, edge_feat, src_idx, tgt_idx, W, b, out);
}

// round 14
// speedup vs baseline: 1.0564x; 1.0564x over previous
#include <cuda_runtime.h>
#include <cuda_fp16.h>
#include <cstdint>

// ============================================================================
// ConvolutionFromEdgeSetUpdate:
//   messages = relu([node[src] | node[tgt] | edge] @ W + b)   (E x 64)
//   out      = segment_sum(messages, tgt, 50000)
// E=800000, D=64, U=64, K=192.
//
// R14 = split-K register-B (R12) + single-barrier pipeline (R11) via a
// DEFERRED epilogue: warps = mg(2) x ng(2) x kg(2); B frags live in 48 regs
// (no steady-state B-ldsm); kg partners exchange the give-away 16-row acc
// block through double-buffered SMEM, and the combine+bias+relu+red for
// tile t runs at the TOP of iteration t+1 — after the one barrier that
// already exists for the A-buffer swap. 1 barrier/tile, L1 work -33%.
// ============================================================================

#define NN_NODES 50000
#define NN_EDGES 800000
#define D_FEAT   64
#define UNITS    64
#define KDIM     192
#define TILE_M   64
#define N_TILES  (NN_EDGES / TILE_M)   // 12500
#define THREADS  256                   // 8 warps: 2 mg x 2 ng x 2 kg
#define GRID_X   296                   // 2 CTAs per SM

// SMEM: padded rows (200 fp16 = 400B) as in R11/R12.
#define STRIDE_B   400
#define SM_A0      0
#define SM_A1      (SM_A0 + TILE_M * STRIDE_B)       // 25600
#define SM_B       (SM_A1 + TILE_M * STRIDE_B)       // 51200
#define SM_IDX     (SM_B + UNITS * STRIDE_B)         // 76800: 2 bufs x 128 int
#define SM_P       (SM_IDX + 2 * 128 * 4)            // 77824: 2 bufs x 16KB
#define SM_TOTAL   (SM_P + 2 * 16384)                // 110592 -> 2 CTAs/SM

// ---------------- helpers ----------------

__device__ __forceinline__ uint32_t smem_to_u32(const void* smem_ptr) {
    uint32_t addr;
    asm("{ .reg .u64 tmp; cvta.to.shared.u64 tmp, %1; cvt.u32.u64 %0, tmp; }"
        : "=r"(addr) : "l"(smem_ptr));
    return addr;
}

__device__ __forceinline__ void ldsm_x4(uint32_t* r, uint32_t addr) {
    asm volatile("ldmatrix.sync.aligned.m8n8.x4.shared.b16 {%0,%1,%2,%3}, [%4];"
        : "=r"(r[0]), "=r"(r[1]), "=r"(r[2]), "=r"(r[3]) : "r"(addr));
}

__device__ __forceinline__ void ldsm_x2(uint32_t* r, uint32_t addr) {
    asm volatile("ldmatrix.sync.aligned.m8n8.x2.shared.b16 {%0,%1}, [%2];"
        : "=r"(r[0]), "=r"(r[1]) : "r"(addr));
}

__device__ __forceinline__ void mma_f16(float* c, const uint32_t* a, const uint32_t* b) {
    asm volatile(
        "mma.sync.aligned.m16n8k16.row.col.f32.f16.f16.f32 "
        "{%0,%1,%2,%3}, {%4,%5,%6,%7}, {%8,%9}, {%0,%1,%2,%3};"
        : "+f"(c[0]), "+f"(c[1]), "+f"(c[2]), "+f"(c[3])
        : "r"(a[0]), "r"(a[1]), "r"(a[2]), "r"(a[3]), "r"(b[0]), "r"(b[1]));
}

__device__ __forceinline__ uint32_t pack_h2(float a, float b) {
    __half2 t = __halves2half2(__float2half_rn(a), __float2half_rn(b));
    return *reinterpret_cast<uint32_t*>(&t);
}

// ---------------- zero output (d_out is poisoned 0xAA) ----------------

__global__ void zero_out_kernel(float4* out) {
    int i = blockIdx.x * blockDim.x + threadIdx.x;
    if (i < NN_NODES * UNITS / 4) out[i] = make_float4(0.f, 0.f, 0.f, 0.f);
}

// ---------------- main fused kernel ----------------

__global__ __launch_bounds__(THREADS, 2)
void edgeconv_kernel(const float* __restrict__ node_feat,
                     const float* __restrict__ edge_feat,
                     const int*   __restrict__ src_idx,
                     const int*   __restrict__ tgt_idx,
                     const float* __restrict__ W,
                     const float* __restrict__ bias,
                     float*       __restrict__ out)
{
    extern __shared__ char smem[];
    const uint32_t smem_base = smem_to_u32(smem);
    const int tid  = threadIdx.x;
    const int wid  = tid >> 5;
    const int lane = tid & 31;

    int* const idx_sm = reinterpret_cast<int*>(smem + SM_IDX);

    // ---- build B = W^T (single fp16) in SMEM: Bsm[n][k], k contiguous ----
    for (int task = tid; task < 192; task += THREADS) {
        const int n = task & 63, bseg = task >> 6;
        char* rowp = smem + SM_B + n * STRIDE_B;
        #pragma unroll 8
        for (int j = 0; j < 64; ++j) {
            const int k = bseg * 64 + j;
            *reinterpret_cast<__half*>(rowp + k * 2) = __float2half_rn(W[k * UNITS + n]);
        }
    }

    // warp decomposition: mg(2) x ng(2) x kg(2)
    const int mg = wid >> 2;
    const int ng = (wid >> 1) & 1;
    const int kg = wid & 1;
    const int t4 = lane & 3;
    const int g  = lane >> 2;
    const int r0 = mg * 32 + kg * 16 + g;   // kept epilogue row (0..63)

    // per-thread bias: cols ng*32 + nb*8 + 2*t4 + {0,1}
    float bj0[4], bj1[4];
    #pragma unroll
    for (int j = 0; j < 4; ++j) {
        bj0[j] = bias[ng * 32 + j * 8 + 2 * t4];
        bj1[j] = bias[ng * 32 + j * 8 + 2 * t4 + 1];
    }

    // ldmatrix lane offsets. k byte offset for this warp's half: kg*96*2 = kg*192.
    // kept A rows = mg*32 + kg*16 ; give-away rows = mg*32 + (1-kg)*16.
    const uint32_t aoffK =
        (uint32_t)((mg * 32 + kg * 16 + (lane & 15)) * STRIDE_B
                   + (lane >> 4) * 16 + kg * 192);
    const uint32_t aoffG =
        (uint32_t)((mg * 32 + (1 - kg) * 16 + (lane & 15)) * STRIDE_B
                   + (lane >> 4) * 16 + kg * 192);
    const uint32_t bB = smem_base + SM_B
        + (uint32_t)((ng * 32 + (lane & 7)) * STRIDE_B
                     + ((lane >> 3) & 1) * 16 + kg * 192);

    // partial-exchange slots: [buf e][warp][nb][lane] -> e*16384 + wid*2048
    //                          + nb*512 + lane*16  (conflict-free 16B ops)
    const uint32_t my_slot = (uint32_t)(wid * 2048 + lane * 16);
    const uint32_t pr_slot = (uint32_t)((wid ^ 1) * 2048 + lane * 16);

    // coalesced gather mapping: 16 threads per (row,seg), one float4 each
    const int g_chunk = tid & 15;
    const int g_rs0   = tid >> 4;

    // ======== prologue: idx(t0) -> buf0 ========
    const int tile0 = blockIdx.x;
    if (tid < 128) {
        const int e = tile0 * TILE_M + (tid & 63);
        idx_sm[tid] = (tid < 64) ? __ldg(src_idx + e) : __ldg(tgt_idx + e);
    }
    __syncthreads();   // B tile + idx(t0) ready

    // ---- preload B frags ONCE: 6 ks x 4 nb x 2 regs = 48 regs ----
    uint32_t breg[6][4][2];
    #pragma unroll
    for (int ks = 0; ks < 6; ++ks)
        #pragma unroll
        for (int nb = 0; nb < 4; ++nb)
            ldsm_x2(breg[ks][nb], bB + (uint32_t)(nb * 8 * STRIDE_B + ks * 32));

    // gather(t0) -> A buf0; tgt regs for t0; stage idx(t0+G) -> buf1
    {
        const int* idxp = idx_sm;
        #pragma unroll
        for (int half = 0; half < 2; ++half) {
            const float* p[6]; int rowv[6], segv[6];
            #pragma unroll
            for (int i = 0; i < 6; ++i) {
                const int rs  = g_rs0 + (half * 6 + i) * 16;
                const int row = rs & (TILE_M - 1);
                const int seg = rs >> 6;
                rowv[i] = row; segv[i] = seg;
                p[i] = (seg == 2)
                     ? edge_feat + (size_t)(tile0 * TILE_M + row) * D_FEAT
                     : node_feat + (size_t)idxp[rs] * D_FEAT;
            }
            float4 v[6];
            #pragma unroll
            for (int i = 0; i < 6; ++i)
                v[i] = __ldg(reinterpret_cast<const float4*>(p[i]) + g_chunk);
            #pragma unroll
            for (int i = 0; i < 6; ++i) {
                uint2 hh;
                hh.x = pack_h2(v[i].x, v[i].y);
                hh.y = pack_h2(v[i].z, v[i].w);
                const uint32_t off =
                    (uint32_t)(rowv[i] * STRIDE_B + segv[i] * 128 + g_chunk * 8);
                *reinterpret_cast<uint2*>(smem + SM_A0 + off) = hh;
            }
        }
    }
    int tgtr0 = idx_sm[64 + r0];
    int tgtr1 = idx_sm[64 + r0 + 8];
    if (tid < 128 && tile0 + GRID_X < N_TILES) {
        const int e = (tile0 + GRID_X) * TILE_M + (tid & 63);
        idx_sm[128 + tid] = (tid < 64) ? __ldg(src_idx + e) : __ldg(tgt_idx + e);
    }
    __syncthreads();   // A buf0 + idx(t0+G) ready

    // ======== pipelined main loop: ONE barrier per tile ========
    float accK[4][4], accG[4][4];
    int etgt0 = 0, etgt1 = 0;     // epilogue targets (tile t-G)
    int p = 0, q = 0, e = 0;

    for (int tile = tile0; tile < N_TILES; tile += GRID_X) {
        const int nxt = tile + GRID_X;
        int ntgt0 = 0, ntgt1 = 0;

        // ---- stage 1: gather(nxt) into A buf p^1 (overlaps everything) ----
        if (nxt < N_TILES) {
            const int* idxp = idx_sm + (q ^ 1) * 128;
            const uint32_t abase = (p ^ 1) ? SM_A1 : SM_A0;
            #pragma unroll
            for (int half = 0; half < 2; ++half) {
                const float* pp[6]; int rowv[6], segv[6];
                #pragma unroll
                for (int i = 0; i < 6; ++i) {
                    const int rs  = g_rs0 + (half * 6 + i) * 16;
                    const int row = rs & (TILE_M - 1);
                    const int seg = rs >> 6;
                    rowv[i] = row; segv[i] = seg;
                    pp[i] = (seg == 2)
                         ? edge_feat + (size_t)(nxt * TILE_M + row) * D_FEAT
                         : node_feat + (size_t)idxp[rs] * D_FEAT;
                }
                float4 v[6];
                #pragma unroll
                for (int i = 0; i < 6; ++i)
                    v[i] = __ldg(reinterpret_cast<const float4*>(pp[i]) + g_chunk);
                #pragma unroll
                for (int i = 0; i < 6; ++i) {
                    uint2 hh;
                    hh.x = pack_h2(v[i].x, v[i].y);
                    hh.y = pack_h2(v[i].z, v[i].w);
                    const uint32_t off =
                        (uint32_t)(rowv[i] * STRIDE_B + segv[i] * 128 + g_chunk * 8);
                    *reinterpret_cast<uint2*>(smem + abase + off) = hh;
                }
            }
            ntgt0 = idxp[64 + r0];
            ntgt1 = idxp[64 + r0 + 8];
            if (tid < 128 && nxt + GRID_X < N_TILES) {
                const int ee = (nxt + GRID_X) * TILE_M + (tid & 63);
                idx_sm[q * 128 + tid] =
                    (tid < 64) ? __ldg(src_idx + ee) : __ldg(tgt_idx + ee);
            }
        }

        // ---- deferred epilogue(tile - G): combine + bias + relu + red ----
        if (tile != tile0) {
            const char* ppart = smem + SM_P + e * 16384 + pr_slot;
            float* o0 = out + (size_t)etgt0 * UNITS + ng * 32 + 2 * t4;
            float* o1 = out + (size_t)etgt1 * UNITS + ng * 32 + 2 * t4;
            #pragma unroll
            for (int nb = 0; nb < 4; ++nb) {
                float4 pr = *reinterpret_cast<const float4*>(ppart + nb * 512);
                float v0 = fmaxf(accK[nb][0] + pr.x + bj0[nb], 0.f);
                float v1 = fmaxf(accK[nb][1] + pr.y + bj1[nb], 0.f);
                float v2 = fmaxf(accK[nb][2] + pr.z + bj0[nb], 0.f);
                float v3 = fmaxf(accK[nb][3] + pr.w + bj1[nb], 0.f);
                asm volatile("red.global.add.v2.f32 [%0], {%1, %2};"
                             :: "l"(o0 + nb * 8), "f"(v0), "f"(v1) : "memory");
                asm volatile("red.global.add.v2.f32 [%0], {%1, %2};"
                             :: "l"(o1 + nb * 8), "f"(v2), "f"(v3) : "memory");
            }
        }

        // ---- stage 2: MMA(tile) from A buf p; B from registers ----
        const uint32_t aBase = smem_base + (p ? SM_A1 : SM_A0);
        const uint32_t aK = aBase + aoffK;
        const uint32_t aG = aBase + aoffG;
        #pragma unroll
        for (int j = 0; j < 4; ++j)
            #pragma unroll
            for (int qq = 0; qq < 4; ++qq) { accK[j][qq] = 0.f; accG[j][qq] = 0.f; }

        #pragma unroll
        for (int ks = 0; ks < 6; ++ks) {   // 6 k-steps (this warp's K half)
            const uint32_t kb = (uint32_t)(ks * 32);
            uint32_t ak[4], ag[4];
            ldsm_x4(ak, aK + kb);
            ldsm_x4(ag, aG + kb);
            #pragma unroll
            for (int nb = 0; nb < 4; ++nb) {
                mma_f16(accK[nb], ak, breg[ks][nb]);
                mma_f16(accG[nb], ag, breg[ks][nb]);
            }
        }

        // ---- store give-away partials into pbuf e^1 ----
        {
            char* mypart = smem + SM_P + (e ^ 1) * 16384 + my_slot;
            #pragma unroll
            for (int nb = 0; nb < 4; ++nb)
                *reinterpret_cast<float4*>(mypart + nb * 512) =
                    make_float4(accG[nb][0], accG[nb][1], accG[nb][2], accG[nb][3]);
        }

        __syncthreads();   // A buf p^1, idx buf q, partials(tile) all visible

        etgt0 = tgtr0; etgt1 = tgtr1;
        tgtr0 = ntgt0; tgtr1 = ntgt1;
        p ^= 1; q ^= 1; e ^= 1;
    }

    // ======== drain: epilogue for the last processed tile ========
    {
        const char* ppart = smem + SM_P + e * 16384 + pr_slot;
        float* o0 = out + (size_t)etgt0 * UNITS + ng * 32 + 2 * t4;
        float* o1 = out + (size_t)etgt1 * UNITS + ng * 32 + 2 * t4;
        #pragma unroll
        for (int nb = 0; nb < 4; ++nb) {
            float4 pr = *reinterpret_cast<const float4*>(ppart + nb * 512);
            float v0 = fmaxf(accK[nb][0] + pr.x + bj0[nb], 0.f);
            float v1 = fmaxf(accK[nb][1] + pr.y + bj1[nb], 0.f);
            float v2 = fmaxf(accK[nb][2] + pr.z + bj0[nb], 0.f);
            float v3 = fmaxf(accK[nb][3] + pr.w + bj1[nb], 0.f);
            asm volatile("red.global.add.v2.f32 [%0], {%1, %2};"
                         :: "l"(o0 + nb * 8), "f"(v0), "f"(v1) : "memory");
            asm volatile("red.global.add.v2.f32 [%0], {%1, %2};"
                         :: "l"(o1 + nb * 8), "f"(v2), "f"(v3) : "memory");
        }
    }
}

// ---------------- launch ----------------

extern "C" void kernel_launch(void* const* d_in, const int* in_sizes, int n_in,
                              void* d_out, int out_size) {
    const float* node_feat = (const float*)d_in[0];
    const float* edge_feat = (const float*)d_in[1];
    const int*   src_idx   = (const int*)d_in[2];
    const int*   tgt_idx   = (const int*)d_in[3];
    const float* W         = (const float*)d_in[4];
    const float* b         = (const float*)d_in[5];
    float* out = (float*)d_out;

    int n4 = NN_NODES * UNITS / 4;
    zero_out_kernel<<<(n4 + 255) / 256, 256>>>((float4*)out);

    static int configured = 0;
    if (!configured) {
        cudaFuncSetAttribute(edgeconv_kernel,
                             cudaFuncAttributeMaxDynamicSharedMemorySize, SM_TOTAL);
        configured = 1;
    }
    edgeconv_kernel<<<GRID_X, THREADS, SM_TOTAL>>>(
        node_feat, edge_feat, src_idx, tgt_idx, W, b, out);
}